// round 14
// baseline (speedup 1.0000x reference)
#include <cuda_runtime.h>
#include <cuda_fp16.h>
#include <mma.h>
#include <math.h>
#include <stdint.h>

using namespace nvcuda;

#define BB 2
#define SS 2048
#define DM 1024
#define NH 16
#define FF 4096
#define MT (BB*SS)   // 4096 rows

// ===================== helpers =====================
union F2U { unsigned long long u; float2 f; };
__device__ __forceinline__ void fma2(F2U& d, const F2U a, const F2U b) {
    asm("fma.rn.f32x2 %0, %1, %2, %0;" : "+l"(d.u) : "l"(a.u), "l"(b.u));
}
__device__ __forceinline__ uint32_t smem_to_u32(const void* p) {
    uint32_t a;
    asm("{ .reg .u64 tmp; cvta.to.shared.u64 tmp, %1; cvt.u32.u64 %0, tmp; }" : "=r"(a) : "l"(p));
    return a;
}
#define CP_ASYNC16(dst, src) \
    asm volatile("cp.async.cg.shared.global [%0], [%1], 16;" :: "r"(dst), "l"(src))
#define CP_COMMIT() asm volatile("cp.async.commit_group;" ::: "memory")
#define CP_WAIT1()  asm volatile("cp.async.wait_group 1;"  ::: "memory")
#define CP_WAIT0()  asm volatile("cp.async.wait_group 0;"  ::: "memory")

// ===================== scratch =====================
__device__ __half g_h1h[MT*DM];
__device__ float  g_q[MT*DM], g_k[MT*DM], g_v[MT*DM];
__device__ __half g_cath[MT*DM];
__device__ float  g_attx[MT*DM];
__device__ __half g_h2h[MT*DM];
__device__ __half g_ff1h[(size_t)MT*FF];
__device__ __half g_wqkvh[3*DM*DM];       // [3072 rows N][1024 K]
__device__ __half g_woh[DM*DM];           // [1024 N][1024 K]
__device__ __half g_w1h[(size_t)DM*FF];   // [4096 N][1024 K]
__device__ __half g_w2h[(size_t)FF*DM];   // [1024 N][4096 K]

// ===================== LayerNorm fp32 -> fp16 =====================
__global__ void ln_half_kernel(const float* __restrict__ x, const float* __restrict__ w,
                               const float* __restrict__ b, __half* __restrict__ o) {
    int row = blockIdx.x;
    int t = threadIdx.x;                       // 256 threads x 4 floats
    const float4* xr = (const float4*)(x + (size_t)row * DM);
    float4 v = xr[t];
    float s  = v.x + v.y + v.z + v.w;
    float ss = v.x*v.x + v.y*v.y + v.z*v.z + v.w*v.w;
    #pragma unroll
    for (int o2 = 16; o2; o2 >>= 1) {
        s  += __shfl_xor_sync(0xffffffffu, s,  o2);
        ss += __shfl_xor_sync(0xffffffffu, ss, o2);
    }
    __shared__ float red[2][8];
    __shared__ float stats[2];
    int lane = t & 31, wid = t >> 5;
    if (lane == 0) { red[0][wid] = s; red[1][wid] = ss; }
    __syncthreads();
    if (t == 0) {
        float S1 = 0.f, S2 = 0.f;
        #pragma unroll
        for (int i = 0; i < 8; i++) { S1 += red[0][i]; S2 += red[1][i]; }
        float mu  = S1 * (1.f / DM);
        float var = S2 * (1.f / DM) - mu * mu;
        stats[0] = mu; stats[1] = rsqrtf(var + 1e-5f);
    }
    __syncthreads();
    float mu = stats[0], rs = stats[1];
    float4 wv = ((const float4*)w)[t];
    float4 bv = ((const float4*)b)[t];
    float y0 = (v.x - mu) * rs * wv.x + bv.x;
    float y1 = (v.y - mu) * rs * wv.y + bv.y;
    float y2 = (v.z - mu) * rs * wv.z + bv.z;
    float y3 = (v.w - mu) * rs * wv.w + bv.w;
    __half2 p0 = __floats2half2_rn(y0, y1);
    __half2 p1 = __floats2half2_rn(y2, y3);
    *(uint2*)(o + (size_t)row * DM + t * 4) =
        make_uint2(*(uint32_t*)&p0, *(uint32_t*)&p1);
}

// ===================== transpose fp32 [R,C] -> fp16 [C,R] =====================
__global__ void thalf_kernel(const float* __restrict__ in, __half* __restrict__ o,
                             int R, int C, size_t inBatch, size_t outBatch) {
    in += (size_t)blockIdx.z * inBatch;
    o  += (size_t)blockIdx.z * outBatch;
    __shared__ float tile[32][33];
    int c0 = blockIdx.x * 32, r0 = blockIdx.y * 32;
    int tx = threadIdx.x, ty = threadIdx.y;   // (32, 8)
    #pragma unroll
    for (int i = 0; i < 4; i++)
        tile[ty + 8*i][tx] = in[(size_t)(r0 + ty + 8*i) * C + c0 + tx];
    __syncthreads();
    #pragma unroll
    for (int i = 0; i < 4; i++) {
        float v = tile[tx][ty + 8*i];
        o[(size_t)(c0 + ty + 8*i) * R + r0 + tx] = __float2half_rn(v);
    }
}

// ===================== fp16 single-term wmma GEMM =====================
// D[M,N] = A[M,K] * B[N,K]^T, fp16 operands (pre-rounded), fp32 accum.
// CTA tile 128x128, 4 warps of 64x64, BK=32, 3-stage cp.async, 2 CTAs/SM.
// EPI: 0 = QKV scatter -> q/k/v [b,h,s,e] fp32
//      1 = +resid -> fp32 row-major
//      2 = +bias, exact GELU -> fp16
//      3 = +bias, +resid -> fp32 row-major
#define TILEB   10240              // one 128x32 fp16 tile, row pitch 80B (40 halves)
#define STG2    (2*TILEB)          // A,B per stage = 20480
#define GSMEM   67584              // max(3*STG2=61440, epilogue 128*132*4)

template<int EPI>
__global__ __launch_bounds__(128, 2)
void gemmh(const __half* __restrict__ A, const __half* __restrict__ B, int K,
           float* __restrict__ out0, float* __restrict__ out1, float* __restrict__ out2,
           __half* __restrict__ oh,
           const float* __restrict__ bias, const float* __restrict__ resid, int N)
{
    extern __shared__ __align__(16) uint8_t smraw[];
    const uint32_t smb = smem_to_u32(smraw);
    const int tid = threadIdx.x;
    const int wid = tid >> 5;
    const int wm = wid >> 1, wn = wid & 1;     // 2x2 warp grid, 64x64 each
    const int m0 = blockIdx.y * 128;
    const int n0 = blockIdx.x * 128;

    const __half* gsrc[2] = { A + (size_t)m0 * K, B + (size_t)n0 * K };

    wmma::fragment<wmma::accumulator, 16, 16, 16, float> acc[4][4];
    #pragma unroll
    for (int i = 0; i < 4; i++)
        #pragma unroll
        for (int j = 0; j < 4; j++) wmma::fill_fragment(acc[i][j], 0.0f);

    const int NCH = K >> 5;

    // async load of chunk ch into stage st: 2 tiles x 128 rows x 4 x 16B = 1024 ops
    auto issue = [&](int ch, int st) {
        int k0 = ch << 5;
        #pragma unroll
        for (int i = 0; i < 8; i++) {
            int idx = i * 128 + tid;
            int t2  = idx >> 9;
            int rem = idx & 511;
            int row = rem >> 2;
            int cch = rem & 3;
            uint32_t dst = smb + st * STG2 + t2 * TILEB + row * 80 + cch * 16;
            const __half* src = gsrc[t2] + (size_t)row * K + k0 + cch * 8;
            CP_ASYNC16(dst, src);
        }
        CP_COMMIT();
    };

    issue(0, 0);
    if (NCH > 1) issue(1, 1);

    for (int ch = 0; ch < NCH; ch++) {
        if (ch == NCH - 1) { CP_WAIT0(); } else { CP_WAIT1(); }
        __syncthreads();
        if (ch + 2 < NCH) issue(ch + 2, (ch + 2) % 3);
        const int st = ch % 3;
        const __half* As = (const __half*)(smraw + st * STG2);
        const __half* Bs = (const __half*)(smraw + st * STG2 + TILEB);
        #pragma unroll
        for (int kk = 0; kk < 32; kk += 16) {
            wmma::fragment<wmma::matrix_a, 16, 16, 16, __half, wmma::row_major> af[4];
            #pragma unroll
            for (int i = 0; i < 4; i++)
                wmma::load_matrix_sync(af[i], As + (wm * 64 + i * 16) * 40 + kk, 40);
            #pragma unroll
            for (int j = 0; j < 4; j++) {
                wmma::fragment<wmma::matrix_b, 16, 16, 16, __half, wmma::col_major> bf;
                wmma::load_matrix_sync(bf, Bs + (wn * 64 + j * 16) * 40 + kk, 40);
                #pragma unroll
                for (int i = 0; i < 4; i++)
                    wmma::mma_sync(acc[i][j], af[i], bf, acc[i][j]);
            }
        }
    }

    // ---- epilogue through smem (reuses stage smem: sync first) ----
    __syncthreads();
    float* Cs = (float*)smraw;        // [128][132]
    #pragma unroll
    for (int i = 0; i < 4; i++)
        #pragma unroll
        for (int j = 0; j < 4; j++)
            wmma::store_matrix_sync(Cs + (wm * 64 + i * 16) * 132 + (wn * 64 + j * 16),
                                    acc[i][j], 132, wmma::mem_row_major);
    __syncthreads();

    #pragma unroll
    for (int it = 0; it < 32; it++) {
        int idx = it * 128 + tid;
        int r  = idx >> 5;
        int c4 = (idx & 31) << 2;
        float4 vv = *(const float4*)(Cs + r * 132 + c4);
        int row = m0 + r;
        int c   = n0 + c4;
        if (EPI == 0) {
            int b = row >> 11, sq = row & 2047;
            int proj = c >> 10, cc = c & 1023, hh = cc >> 6, e0 = cc & 63;
            float* base = (proj == 0) ? out0 : (proj == 1) ? out1 : out2;
            *(float4*)(base + ((size_t)(b * NH + hh) * SS + sq) * 64 + e0) = vv;
        } else if (EPI == 1) {
            float4 r4 = *(const float4*)(resid + (size_t)row * N + c);
            vv.x += r4.x; vv.y += r4.y; vv.z += r4.z; vv.w += r4.w;
            *(float4*)(out0 + (size_t)row * N + c) = vv;
        } else if (EPI == 2) {
            float4 b4 = *(const float4*)(bias + c);
            float o0 = vv.x + b4.x, o1 = vv.y + b4.y, o2 = vv.z + b4.z, o3 = vv.w + b4.w;
            o0 = 0.5f * o0 * (1.f + erff(o0 * 0.70710678118f));
            o1 = 0.5f * o1 * (1.f + erff(o1 * 0.70710678118f));
            o2 = 0.5f * o2 * (1.f + erff(o2 * 0.70710678118f));
            o3 = 0.5f * o3 * (1.f + erff(o3 * 0.70710678118f));
            __half2 p0 = __floats2half2_rn(o0, o1);
            __half2 p1 = __floats2half2_rn(o2, o3);
            *(uint2*)(oh + (size_t)row * N + c) =
                make_uint2(*(uint32_t*)&p0, *(uint32_t*)&p1);
        } else {  // EPI == 3
            float4 b4 = *(const float4*)(bias + c);
            float4 r4 = *(const float4*)(resid + (size_t)row * N + c);
            vv.x += b4.x + r4.x; vv.y += b4.y + r4.y;
            vv.z += b4.z + r4.z; vv.w += b4.w + r4.w;
            *(float4*)(out0 + (size_t)row * N + c) = vv;
        }
    }
}

// ===================== causal flash attention (fp32 fma2, f16x2 exp) -> fp16 concat =====================
__global__ void attn_kernel(const float* __restrict__ Q, const float* __restrict__ Kg,
                            const float* __restrict__ Vg, __half* __restrict__ Oh)
{
    __shared__ __align__(16) float KV[64][64];
    __shared__ float sc[64][65];
    int t  = threadIdx.x;
    int qt = blockIdx.x;
    int bh = blockIdx.y;
    int qi = qt * 64 + t;
    const float LOG2E = 1.44269504f;

    const float* qrow = Q + ((size_t)bh * SS + qi) * 64;
    F2U qp[32];
    #pragma unroll
    for (int e = 0; e < 32; e += 2) {
        float4 f = *(const float4*)(qrow + 2 * e);
        qp[e].f     = make_float2(f.x, f.y);
        qp[e + 1].f = make_float2(f.z, f.w);
    }
    F2U accp[32];
    #pragma unroll
    for (int e = 0; e < 32; e++) accp[e].u = 0ull;
    float m = -INFINITY, l = 0.f;

    for (int kt = 0; kt <= qt; kt++) {
        int k0 = kt * 64;
        __syncthreads();
        const float* kb = Kg + ((size_t)bh * SS + k0) * 64;
        for (int i = t; i < 64 * 16; i += 64) {
            int r = i >> 4, c = (i & 15) << 2;
            *(float4*)&KV[r][c] = *(const float4*)(kb + r * 64 + c);
        }
        __syncthreads();

        float tmax = -INFINITY;
        for (int j = 0; j < 64; j++) {
            const F2U* kr = (const F2U*)KV[j];
            F2U s2; s2.u = 0ull;
            #pragma unroll
            for (int e = 0; e < 32; e++) fma2(s2, qp[e], kr[e]);
            float s = (s2.f.x + s2.f.y) * 0.125f;
            if (k0 + j > qi) s = -INFINITY;
            sc[t][j] = s;
            tmax = fmaxf(tmax, s);
        }
        float nm   = fmaxf(m, tmax);
        float corr = __expf(m - nm);
        l *= corr;
        #pragma unroll
        for (int e = 0; e < 32; e++) { accp[e].f.x *= corr; accp[e].f.y *= corr; }

        __syncthreads();
        const float* vb = Vg + ((size_t)bh * SS + k0) * 64;
        for (int i = t; i < 64 * 16; i += 64) {
            int r = i >> 4, c = (i & 15) << 2;
            *(float4*)&KV[r][c] = *(const float4*)(vb + r * 64 + c);
        }
        __syncthreads();

        for (int j = 0; j < 64; j += 2) {
            // two scores -> one f16x2 MUFU exp
            float a0 = (sc[t][j]     - nm) * LOG2E;
            float a1 = (sc[t][j + 1] - nm) * LOG2E;
            __half2 harg = __floats2half2_rn(a0, a1);
            uint32_t hp;
            asm("ex2.approx.f16x2 %0, %1;" : "=r"(hp) : "r"(*(uint32_t*)&harg));
            __half2 hval = *(__half2*)&hp;
            float p0 = __low2float(hval);
            float p1 = __high2float(hval);
            l += p0 + p1;
            F2U pd0; pd0.f = make_float2(p0, p0);
            F2U pd1; pd1.f = make_float2(p1, p1);
            const F2U* vr0 = (const F2U*)KV[j];
            const F2U* vr1 = (const F2U*)KV[j + 1];
            #pragma unroll
            for (int e = 0; e < 32; e++) {
                fma2(accp[e], pd0, vr0[e]);
                fma2(accp[e], pd1, vr1[e]);
            }
        }
        m = nm;
    }

    float inv = 1.f / l;
    int b = bh >> 4, hh = bh & 15;
    size_t base = ((size_t)(b * SS + qi)) * DM + hh * 64;
    #pragma unroll
    for (int e = 0; e < 32; e += 2) {
        __half2 p0 = __floats2half2_rn(accp[e].f.x * inv,     accp[e].f.y * inv);
        __half2 p1 = __floats2half2_rn(accp[e + 1].f.x * inv, accp[e + 1].f.y * inv);
        *(uint2*)(Oh + base + 2 * e) = make_uint2(*(uint32_t*)&p0, *(uint32_t*)&p1);
    }
}

// ===================== launch =====================
extern "C" void kernel_launch(void* const* d_in, const int* in_sizes, int n_in,
                              void* d_out, int out_size) {
    const float* x    = (const float*)d_in[0];
    const float* Wq   = (const float*)d_in[2];
    const float* Wk   = (const float*)d_in[3];
    const float* Wv   = (const float*)d_in[4];
    const float* Wo   = (const float*)d_in[5];
    const float* ln1w = (const float*)d_in[6];
    const float* ln1b = (const float*)d_in[7];
    const float* ln2w = (const float*)d_in[8];
    const float* ln2b = (const float*)d_in[9];
    const float* W1   = (const float*)d_in[10];
    const float* b1   = (const float*)d_in[11];
    const float* W2   = (const float*)d_in[12];
    const float* b2   = (const float*)d_in[13];
    float* out = (float*)d_out;

    __half *h1h, *cath, *h2h, *ff1h, *wqkvh, *woh, *w1h, *w2h;
    float *q, *k, *v, *attx;
    cudaGetSymbolAddress((void**)&h1h,   g_h1h);
    cudaGetSymbolAddress((void**)&q,     g_q);
    cudaGetSymbolAddress((void**)&k,     g_k);
    cudaGetSymbolAddress((void**)&v,     g_v);
    cudaGetSymbolAddress((void**)&cath,  g_cath);
    cudaGetSymbolAddress((void**)&attx,  g_attx);
    cudaGetSymbolAddress((void**)&h2h,   g_h2h);
    cudaGetSymbolAddress((void**)&ff1h,  g_ff1h);
    cudaGetSymbolAddress((void**)&wqkvh, g_wqkvh);
    cudaGetSymbolAddress((void**)&woh,   g_woh);
    cudaGetSymbolAddress((void**)&w1h,   g_w1h);
    cudaGetSymbolAddress((void**)&w2h,   g_w2h);

    cudaFuncSetAttribute(gemmh<0>, cudaFuncAttributeMaxDynamicSharedMemorySize, GSMEM);
    cudaFuncSetAttribute(gemmh<1>, cudaFuncAttributeMaxDynamicSharedMemorySize, GSMEM);
    cudaFuncSetAttribute(gemmh<2>, cudaFuncAttributeMaxDynamicSharedMemorySize, GSMEM);
    cudaFuncSetAttribute(gemmh<3>, cudaFuncAttributeMaxDynamicSharedMemorySize, GSMEM);

    dim3 t32x8(32, 8);

    // LN1 -> fp16
    ln_half_kernel<<<MT, 256>>>(x, ln1w, ln1b, h1h);

    // weight transpose -> fp16 [N,K]
    thalf_kernel<<<dim3(2, 32, 16), t32x8>>>(Wq, wqkvh,               1024, 64, (size_t)1024*64, (size_t)64*1024);
    thalf_kernel<<<dim3(2, 32, 16), t32x8>>>(Wk, wqkvh + 1024*1024,   1024, 64, (size_t)1024*64, (size_t)64*1024);
    thalf_kernel<<<dim3(2, 32, 16), t32x8>>>(Wv, wqkvh + 2*1024*1024, 1024, 64, (size_t)1024*64, (size_t)64*1024);
    thalf_kernel<<<dim3(32, 32, 1),  t32x8>>>(Wo, woh, 1024, 1024, 0, 0);
    thalf_kernel<<<dim3(128, 32, 1), t32x8>>>(W1, w1h, 1024, 4096, 0, 0);
    thalf_kernel<<<dim3(32, 128, 1), t32x8>>>(W2, w2h, 4096, 1024, 0, 0);

    // QKV fused GEMM: M=4096, N=3072, K=1024 -> q/k/v fp32 [b,h,s,e]
    gemmh<0><<<dim3(24, 32), 128, GSMEM>>>(h1h, wqkvh, 1024,
                                           q, k, v, nullptr, nullptr, nullptr, 0);

    // causal attention -> fp16 concat
    attn_kernel<<<dim3(SS / 64, BB * NH), 64>>>(q, k, v, cath);

    // Wo + residual(x) -> attx fp32
    gemmh<1><<<dim3(8, 32), 128, GSMEM>>>(cath, woh, 1024,
                                          attx, nullptr, nullptr, nullptr, nullptr, x, DM);

    // LN2 -> fp16
    ln_half_kernel<<<MT, 256>>>(attx, ln2w, ln2b, h2h);

    // FFN1 + bias + exact GELU -> fp16 ff1
    gemmh<2><<<dim3(32, 32), 128, GSMEM>>>(h2h, w1h, 1024,
                                           nullptr, nullptr, nullptr, ff1h, b1, nullptr, FF);

    // FFN2 + bias + residual(attx) -> d_out fp32
    gemmh<3><<<dim3(8, 32), 128, GSMEM>>>(ff1h, w2h, 4096,
                                          out, nullptr, nullptr, nullptr, b2, attx, DM);
}

// round 15
// speedup vs baseline: 2.4998x; 2.4998x over previous
#include <cuda_runtime.h>
#include <cuda_fp16.h>
#include <mma.h>
#include <math.h>
#include <stdint.h>

using namespace nvcuda;

#define BB 2
#define SS 2048
#define DM 1024
#define NH 16
#define FF 4096
#define MT (BB*SS)   // 4096 rows

// ===================== helpers =====================
__device__ __forceinline__ uint32_t smem_to_u32(const void* p) {
    uint32_t a;
    asm("{ .reg .u64 tmp; cvta.to.shared.u64 tmp, %1; cvt.u32.u64 %0, tmp; }" : "=r"(a) : "l"(p));
    return a;
}
#define CP_ASYNC16(dst, src) \
    asm volatile("cp.async.cg.shared.global [%0], [%1], 16;" :: "r"(dst), "l"(src))
#define CP_COMMIT() asm volatile("cp.async.commit_group;" ::: "memory")
#define CP_WAIT1()  asm volatile("cp.async.wait_group 1;"  ::: "memory")
#define CP_WAIT0()  asm volatile("cp.async.wait_group 0;"  ::: "memory")

#define MMA16816(d, a0, a1, a2, a3, b0, b1) \
    asm volatile("mma.sync.aligned.m16n8k16.row.col.f32.f16.f16.f32 " \
        "{%0,%1,%2,%3}, {%4,%5,%6,%7}, {%8,%9}, {%0,%1,%2,%3};" \
        : "+f"((d)[0]), "+f"((d)[1]), "+f"((d)[2]), "+f"((d)[3]) \
        : "r"(a0), "r"(a1), "r"(a2), "r"(a3), "r"(b0), "r"(b1))

#define LDSM4(r0, r1, r2, r3, addr) \
    asm volatile("ldmatrix.sync.aligned.m8n8.x4.shared.b16 {%0,%1,%2,%3}, [%4];" \
        : "=r"(r0), "=r"(r1), "=r"(r2), "=r"(r3) : "r"(addr))

#define LDSM4T(r0, r1, r2, r3, addr) \
    asm volatile("ldmatrix.sync.aligned.m8n8.x4.trans.shared.b16 {%0,%1,%2,%3}, [%4];" \
        : "=r"(r0), "=r"(r1), "=r"(r2), "=r"(r3) : "r"(addr))

// ===================== scratch =====================
__device__ __half g_h1h[MT*DM];
__device__ __half g_qkvh[(size_t)3*MT*DM];   // [proj][b*NH+h][s][64] fp16
__device__ __half g_cath[MT*DM];
__device__ float  g_attx[MT*DM];
__device__ __half g_h2h[MT*DM];
__device__ __half g_ff1h[(size_t)MT*FF];
__device__ __half g_wqkvh[3*DM*DM];       // [3072 N][1024 K]
__device__ __half g_woh[DM*DM];
__device__ __half g_w1h[(size_t)DM*FF];
__device__ __half g_w2h[(size_t)FF*DM];

// ===================== LayerNorm fp32 -> fp16 =====================
__global__ void ln_half_kernel(const float* __restrict__ x, const float* __restrict__ w,
                               const float* __restrict__ b, __half* __restrict__ o) {
    int row = blockIdx.x;
    int t = threadIdx.x;
    const float4* xr = (const float4*)(x + (size_t)row * DM);
    float4 v = xr[t];
    float s  = v.x + v.y + v.z + v.w;
    float ss = v.x*v.x + v.y*v.y + v.z*v.z + v.w*v.w;
    #pragma unroll
    for (int o2 = 16; o2; o2 >>= 1) {
        s  += __shfl_xor_sync(0xffffffffu, s,  o2);
        ss += __shfl_xor_sync(0xffffffffu, ss, o2);
    }
    __shared__ float red[2][8];
    __shared__ float stats[2];
    int lane = t & 31, wid = t >> 5;
    if (lane == 0) { red[0][wid] = s; red[1][wid] = ss; }
    __syncthreads();
    if (t == 0) {
        float S1 = 0.f, S2 = 0.f;
        #pragma unroll
        for (int i = 0; i < 8; i++) { S1 += red[0][i]; S2 += red[1][i]; }
        float mu  = S1 * (1.f / DM);
        float var = S2 * (1.f / DM) - mu * mu;
        stats[0] = mu; stats[1] = rsqrtf(var + 1e-5f);
    }
    __syncthreads();
    float mu = stats[0], rs = stats[1];
    float4 wv = ((const float4*)w)[t];
    float4 bv = ((const float4*)b)[t];
    float y0 = (v.x - mu) * rs * wv.x + bv.x;
    float y1 = (v.y - mu) * rs * wv.y + bv.y;
    float y2 = (v.z - mu) * rs * wv.z + bv.z;
    float y3 = (v.w - mu) * rs * wv.w + bv.w;
    __half2 p0 = __floats2half2_rn(y0, y1);
    __half2 p1 = __floats2half2_rn(y2, y3);
    *(uint2*)(o + (size_t)row * DM + t * 4) =
        make_uint2(*(uint32_t*)&p0, *(uint32_t*)&p1);
}

// ===================== transpose fp32 [R,C] -> fp16 [C,R] =====================
__global__ void thalf_kernel(const float* __restrict__ in, __half* __restrict__ o,
                             int R, int C, size_t inBatch, size_t outBatch) {
    in += (size_t)blockIdx.z * inBatch;
    o  += (size_t)blockIdx.z * outBatch;
    __shared__ float tile[32][33];
    int c0 = blockIdx.x * 32, r0 = blockIdx.y * 32;
    int tx = threadIdx.x, ty = threadIdx.y;   // (32, 8)
    #pragma unroll
    for (int i = 0; i < 4; i++)
        tile[ty + 8*i][tx] = in[(size_t)(r0 + ty + 8*i) * C + c0 + tx];
    __syncthreads();
    #pragma unroll
    for (int i = 0; i < 4; i++) {
        float v = tile[tx][ty + 8*i];
        o[(size_t)(c0 + ty + 8*i) * R + r0 + tx] = __float2half_rn(v);
    }
}

// ===================== fp16 wmma GEMM =====================
// D[M,N] = A[M,K] * B[N,K]^T, fp32 accum. 128x128 CTA, 4 warps 64x64, BK=32, 3-stage.
// EPI: 0 = QKV scatter -> fp16 [proj][b,h,s,e]; 1 = +resid fp32; 2 = +bias GELU fp16; 3 = +bias+resid fp32
#define TILEB   10240
#define STG2    (2*TILEB)
#define GSMEM   67584

template<int EPI>
__global__ __launch_bounds__(128, 2)
void gemmh(const __half* __restrict__ A, const __half* __restrict__ B, int K,
           float* __restrict__ out0, __half* __restrict__ oh,
           const float* __restrict__ bias, const float* __restrict__ resid, int N)
{
    extern __shared__ __align__(16) uint8_t smraw[];
    const uint32_t smb = smem_to_u32(smraw);
    const int tid = threadIdx.x;
    const int wid = tid >> 5;
    const int wm = wid >> 1, wn = wid & 1;
    const int m0 = blockIdx.y * 128;
    const int n0 = blockIdx.x * 128;

    const __half* gsrc[2] = { A + (size_t)m0 * K, B + (size_t)n0 * K };

    wmma::fragment<wmma::accumulator, 16, 16, 16, float> acc[4][4];
    #pragma unroll
    for (int i = 0; i < 4; i++)
        #pragma unroll
        for (int j = 0; j < 4; j++) wmma::fill_fragment(acc[i][j], 0.0f);

    const int NCH = K >> 5;

    auto issue = [&](int ch, int st) {
        int k0 = ch << 5;
        #pragma unroll
        for (int i = 0; i < 8; i++) {
            int idx = i * 128 + tid;
            int t2  = idx >> 9;
            int rem = idx & 511;
            int row = rem >> 2;
            int cch = rem & 3;
            uint32_t dst = smb + st * STG2 + t2 * TILEB + row * 80 + cch * 16;
            const __half* src = gsrc[t2] + (size_t)row * K + k0 + cch * 8;
            CP_ASYNC16(dst, src);
        }
        CP_COMMIT();
    };

    issue(0, 0);
    if (NCH > 1) issue(1, 1);

    for (int ch = 0; ch < NCH; ch++) {
        if (ch == NCH - 1) { CP_WAIT0(); } else { CP_WAIT1(); }
        __syncthreads();
        if (ch + 2 < NCH) issue(ch + 2, (ch + 2) % 3);
        const int st = ch % 3;
        const __half* As = (const __half*)(smraw + st * STG2);
        const __half* Bs = (const __half*)(smraw + st * STG2 + TILEB);
        #pragma unroll
        for (int kk = 0; kk < 32; kk += 16) {
            wmma::fragment<wmma::matrix_a, 16, 16, 16, __half, wmma::row_major> af[4];
            #pragma unroll
            for (int i = 0; i < 4; i++)
                wmma::load_matrix_sync(af[i], As + (wm * 64 + i * 16) * 40 + kk, 40);
            #pragma unroll
            for (int j = 0; j < 4; j++) {
                wmma::fragment<wmma::matrix_b, 16, 16, 16, __half, wmma::col_major> bf;
                wmma::load_matrix_sync(bf, Bs + (wn * 64 + j * 16) * 40 + kk, 40);
                #pragma unroll
                for (int i = 0; i < 4; i++)
                    wmma::mma_sync(acc[i][j], af[i], bf, acc[i][j]);
            }
        }
    }

    __syncthreads();
    float* Cs = (float*)smraw;        // [128][132]
    #pragma unroll
    for (int i = 0; i < 4; i++)
        #pragma unroll
        for (int j = 0; j < 4; j++)
            wmma::store_matrix_sync(Cs + (wm * 64 + i * 16) * 132 + (wn * 64 + j * 16),
                                    acc[i][j], 132, wmma::mem_row_major);
    __syncthreads();

    #pragma unroll
    for (int it = 0; it < 32; it++) {
        int idx = it * 128 + tid;
        int r  = idx >> 5;
        int c4 = (idx & 31) << 2;
        float4 vv = *(const float4*)(Cs + r * 132 + c4);
        int row = m0 + r;
        int c   = n0 + c4;
        if (EPI == 0) {
            int b = row >> 11, sq = row & 2047;
            int proj = c >> 10, cc = c & 1023, hh = cc >> 6, e0 = cc & 63;
            __half2 p0 = __floats2half2_rn(vv.x, vv.y);
            __half2 p1 = __floats2half2_rn(vv.z, vv.w);
            *(uint2*)(oh + ((size_t)(proj * BB * NH + b * NH + hh) * SS + sq) * 64 + e0) =
                make_uint2(*(uint32_t*)&p0, *(uint32_t*)&p1);
        } else if (EPI == 1) {
            float4 r4 = *(const float4*)(resid + (size_t)row * N + c);
            vv.x += r4.x; vv.y += r4.y; vv.z += r4.z; vv.w += r4.w;
            *(float4*)(out0 + (size_t)row * N + c) = vv;
        } else if (EPI == 2) {
            float4 b4 = *(const float4*)(bias + c);
            float o0 = vv.x + b4.x, o1 = vv.y + b4.y, o2 = vv.z + b4.z, o3 = vv.w + b4.w;
            o0 = 0.5f * o0 * (1.f + erff(o0 * 0.70710678118f));
            o1 = 0.5f * o1 * (1.f + erff(o1 * 0.70710678118f));
            o2 = 0.5f * o2 * (1.f + erff(o2 * 0.70710678118f));
            o3 = 0.5f * o3 * (1.f + erff(o3 * 0.70710678118f));
            __half2 p0 = __floats2half2_rn(o0, o1);
            __half2 p1 = __floats2half2_rn(o2, o3);
            *(uint2*)(oh + (size_t)row * N + c) =
                make_uint2(*(uint32_t*)&p0, *(uint32_t*)&p1);
        } else {
            float4 b4 = *(const float4*)(bias + c);
            float4 r4 = *(const float4*)(resid + (size_t)row * N + c);
            vv.x += b4.x + r4.x; vv.y += b4.y + r4.y;
            vv.z += b4.z + r4.z; vv.w += b4.w + r4.w;
            *(float4*)(out0 + (size_t)row * N + c) = vv;
        }
    }
}

// ===================== tensor-core causal flash attention (FA2, mma.sync) =====================
// grid (SS/64, BB*NH), 128 threads (4 warps x 16 query rows). fp16 in/out, fp32 softmax/accum.
#define KVPITCH 72

__global__ __launch_bounds__(128)
void attn_kernel(const __half* __restrict__ QKV, __half* __restrict__ Oh)
{
    __shared__ __align__(16) __half sm[2][2][64 * KVPITCH];  // [stage][K/V][row*pitch]
    int tid = threadIdx.x;
    int w = tid >> 5, lane = tid & 31;
    int g = lane >> 2, t4 = lane & 3;
    int qt = blockIdx.x, bh = blockIdx.y;
    int qi0 = qt * 64 + w * 16;

    const __half* Qp = QKV + (size_t)bh * SS * 64;
    const __half* Kp = QKV + (size_t)(BB * NH + bh) * SS * 64;
    const __half* Vp = QKV + (size_t)(2 * BB * NH + bh) * SS * 64;

    // Q A-fragments, pre-scaled by 0.125 * log2(e)
    uint32_t qa[4][4];
    {
        __half2 s2 = __float2half2_rn(0.18033688f);
        int r0 = qi0 + g, r1 = r0 + 8;
        #pragma unroll
        for (int t = 0; t < 4; t++) {
            int c0 = t * 16 + t4 * 2;
            __half2 v;
            v = *(const __half2*)(Qp + (size_t)r0 * 64 + c0);     v = __hmul2(v, s2); qa[t][0] = *(uint32_t*)&v;
            v = *(const __half2*)(Qp + (size_t)r1 * 64 + c0);     v = __hmul2(v, s2); qa[t][1] = *(uint32_t*)&v;
            v = *(const __half2*)(Qp + (size_t)r0 * 64 + c0 + 8); v = __hmul2(v, s2); qa[t][2] = *(uint32_t*)&v;
            v = *(const __half2*)(Qp + (size_t)r1 * 64 + c0 + 8); v = __hmul2(v, s2); qa[t][3] = *(uint32_t*)&v;
        }
    }

    float o[8][4];
    #pragma unroll
    for (int j = 0; j < 8; j++)
        #pragma unroll
        for (int c = 0; c < 4; c++) o[j][c] = 0.f;
    float m0 = -INFINITY, m1 = -INFINITY, l0 = 0.f, l1 = 0.f;

    auto loadKV = [&](int kt, int st) {
        const __half* kb = Kp + (size_t)kt * 64 * 64;
        const __half* vb = Vp + (size_t)kt * 64 * 64;
        #pragma unroll
        for (int i = 0; i < 4; i++) {
            int idx = i * 128 + tid;
            int r = idx >> 3, c = idx & 7;
            CP_ASYNC16(smem_to_u32(&sm[st][0][r * KVPITCH + c * 8]), kb + r * 64 + c * 8);
            CP_ASYNC16(smem_to_u32(&sm[st][1][r * KVPITCH + c * 8]), vb + r * 64 + c * 8);
        }
        CP_COMMIT();
    };

    loadKV(0, 0);
    if (qt > 0) loadKV(1, 1);

    for (int kt = 0; kt <= qt; kt++) {
        if (kt == qt) { CP_WAIT0(); } else { CP_WAIT1(); }
        __syncthreads();
        int st = kt & 1;
        const __half* Ks = sm[st][0];
        const __half* Vs = sm[st][1];

        // ---- S = Q K^T (scaled, log2 units) ----
        float s[8][4];
        #pragma unroll
        for (int j = 0; j < 8; j++)
            #pragma unroll
            for (int c = 0; c < 4; c++) s[j][c] = 0.f;
        int blk = lane >> 3, li = lane & 7;
        #pragma unroll
        for (int j2 = 0; j2 < 4; j2++) {
            #pragma unroll
            for (int t = 0; t < 4; t++) {
                uint32_t addr = smem_to_u32(Ks + (8 * (2 * j2 + (blk >> 1)) + li) * KVPITCH
                                               + t * 16 + (blk & 1) * 8);
                uint32_t r0, r1, r2, r3;
                LDSM4(r0, r1, r2, r3, addr);
                MMA16816(s[2 * j2],     qa[t][0], qa[t][1], qa[t][2], qa[t][3], r0, r1);
                MMA16816(s[2 * j2 + 1], qa[t][0], qa[t][1], qa[t][2], qa[t][3], r2, r3);
            }
        }
        // ---- causal mask (diagonal tile only) ----
        if (kt == qt) {
            int rl0 = w * 16 + g, rl1 = rl0 + 8;
            #pragma unroll
            for (int j = 0; j < 8; j++) {
                int key0 = j * 8 + t4 * 2;
                if (key0     > rl0) s[j][0] = -INFINITY;
                if (key0 + 1 > rl0) s[j][1] = -INFINITY;
                if (key0     > rl1) s[j][2] = -INFINITY;
                if (key0 + 1 > rl1) s[j][3] = -INFINITY;
            }
        }
        // ---- online softmax ----
        float tm0 = -INFINITY, tm1 = -INFINITY;
        #pragma unroll
        for (int j = 0; j < 8; j++) {
            tm0 = fmaxf(tm0, fmaxf(s[j][0], s[j][1]));
            tm1 = fmaxf(tm1, fmaxf(s[j][2], s[j][3]));
        }
        tm0 = fmaxf(tm0, __shfl_xor_sync(0xffffffffu, tm0, 1));
        tm0 = fmaxf(tm0, __shfl_xor_sync(0xffffffffu, tm0, 2));
        tm1 = fmaxf(tm1, __shfl_xor_sync(0xffffffffu, tm1, 1));
        tm1 = fmaxf(tm1, __shfl_xor_sync(0xffffffffu, tm1, 2));
        float nm0 = fmaxf(m0, tm0), nm1 = fmaxf(m1, tm1);
        float cr0 = exp2f(m0 - nm0), cr1 = exp2f(m1 - nm1);
        l0 *= cr0; l1 *= cr1;
        #pragma unroll
        for (int j = 0; j < 8; j++) {
            o[j][0] *= cr0; o[j][1] *= cr0;
            o[j][2] *= cr1; o[j][3] *= cr1;
        }
        m0 = nm0; m1 = nm1;

        uint32_t ph[8][2];
        #pragma unroll
        for (int j = 0; j < 8; j++) {
            __half2 h0 = __floats2half2_rn(s[j][0] - nm0, s[j][1] - nm0);
            __half2 h1 = __floats2half2_rn(s[j][2] - nm1, s[j][3] - nm1);
            asm("ex2.approx.f16x2 %0, %1;" : "=r"(ph[j][0]) : "r"(*(uint32_t*)&h0));
            asm("ex2.approx.f16x2 %0, %1;" : "=r"(ph[j][1]) : "r"(*(uint32_t*)&h1));
            float2 f0 = __half22float2(*(__half2*)&ph[j][0]);
            float2 f1 = __half22float2(*(__half2*)&ph[j][1]);
            l0 += f0.x + f0.y;
            l1 += f1.x + f1.y;
        }

        // ---- O += P V ----
        #pragma unroll
        for (int j2 = 0; j2 < 4; j2++) {
            #pragma unroll
            for (int t = 0; t < 4; t++) {
                uint32_t addr = smem_to_u32(Vs + (t * 16 + (blk & 1) * 8 + li) * KVPITCH
                                               + (2 * j2 + (blk >> 1)) * 8);
                uint32_t r0, r1, r2, r3;
                LDSM4T(r0, r1, r2, r3, addr);
                MMA16816(o[2 * j2],     ph[2*t][0], ph[2*t][1], ph[2*t+1][0], ph[2*t+1][1], r0, r1);
                MMA16816(o[2 * j2 + 1], ph[2*t][0], ph[2*t][1], ph[2*t+1][0], ph[2*t+1][1], r2, r3);
            }
        }
        __syncthreads();
        if (kt + 2 <= qt) loadKV(kt + 2, st);
    }

    // ---- finalize ----
    l0 += __shfl_xor_sync(0xffffffffu, l0, 1);
    l0 += __shfl_xor_sync(0xffffffffu, l0, 2);
    l1 += __shfl_xor_sync(0xffffffffu, l1, 1);
    l1 += __shfl_xor_sync(0xffffffffu, l1, 2);
    float inv0 = 1.f / l0, inv1 = 1.f / l1;
    int b = bh >> 4, h = bh & 15;
    int r0 = qi0 + g, r1 = r0 + 8;
    __half* out0 = Oh + (size_t)(b * SS + r0) * DM + h * 64 + t4 * 2;
    __half* out1 = Oh + (size_t)(b * SS + r1) * DM + h * 64 + t4 * 2;
    #pragma unroll
    for (int j = 0; j < 8; j++) {
        __half2 p0 = __floats2half2_rn(o[j][0] * inv0, o[j][1] * inv0);
        __half2 p1 = __floats2half2_rn(o[j][2] * inv1, o[j][3] * inv1);
        *(uint32_t*)(out0 + j * 8) = *(uint32_t*)&p0;
        *(uint32_t*)(out1 + j * 8) = *(uint32_t*)&p1;
    }
}

// ===================== launch =====================
extern "C" void kernel_launch(void* const* d_in, const int* in_sizes, int n_in,
                              void* d_out, int out_size) {
    const float* x    = (const float*)d_in[0];
    const float* Wq   = (const float*)d_in[2];
    const float* Wk   = (const float*)d_in[3];
    const float* Wv   = (const float*)d_in[4];
    const float* Wo   = (const float*)d_in[5];
    const float* ln1w = (const float*)d_in[6];
    const float* ln1b = (const float*)d_in[7];
    const float* ln2w = (const float*)d_in[8];
    const float* ln2b = (const float*)d_in[9];
    const float* W1   = (const float*)d_in[10];
    const float* b1   = (const float*)d_in[11];
    const float* W2   = (const float*)d_in[12];
    const float* b2   = (const float*)d_in[13];
    float* out = (float*)d_out;

    __half *h1h, *qkvh, *cath, *h2h, *ff1h, *wqkvh, *woh, *w1h, *w2h;
    float *attx;
    cudaGetSymbolAddress((void**)&h1h,   g_h1h);
    cudaGetSymbolAddress((void**)&qkvh,  g_qkvh);
    cudaGetSymbolAddress((void**)&cath,  g_cath);
    cudaGetSymbolAddress((void**)&attx,  g_attx);
    cudaGetSymbolAddress((void**)&h2h,   g_h2h);
    cudaGetSymbolAddress((void**)&ff1h,  g_ff1h);
    cudaGetSymbolAddress((void**)&wqkvh, g_wqkvh);
    cudaGetSymbolAddress((void**)&woh,   g_woh);
    cudaGetSymbolAddress((void**)&w1h,   g_w1h);
    cudaGetSymbolAddress((void**)&w2h,   g_w2h);

    cudaFuncSetAttribute(gemmh<0>, cudaFuncAttributeMaxDynamicSharedMemorySize, GSMEM);
    cudaFuncSetAttribute(gemmh<1>, cudaFuncAttributeMaxDynamicSharedMemorySize, GSMEM);
    cudaFuncSetAttribute(gemmh<2>, cudaFuncAttributeMaxDynamicSharedMemorySize, GSMEM);
    cudaFuncSetAttribute(gemmh<3>, cudaFuncAttributeMaxDynamicSharedMemorySize, GSMEM);

    dim3 t32x8(32, 8);

    // LN1 -> fp16
    ln_half_kernel<<<MT, 256>>>(x, ln1w, ln1b, h1h);

    // weight transpose -> fp16 [N,K]
    thalf_kernel<<<dim3(2, 32, 16), t32x8>>>(Wq, wqkvh,               1024, 64, (size_t)1024*64, (size_t)64*1024);
    thalf_kernel<<<dim3(2, 32, 16), t32x8>>>(Wk, wqkvh + 1024*1024,   1024, 64, (size_t)1024*64, (size_t)64*1024);
    thalf_kernel<<<dim3(2, 32, 16), t32x8>>>(Wv, wqkvh + 2*1024*1024, 1024, 64, (size_t)1024*64, (size_t)64*1024);
    thalf_kernel<<<dim3(32, 32, 1),  t32x8>>>(Wo, woh, 1024, 1024, 0, 0);
    thalf_kernel<<<dim3(128, 32, 1), t32x8>>>(W1, w1h, 1024, 4096, 0, 0);
    thalf_kernel<<<dim3(32, 128, 1), t32x8>>>(W2, w2h, 4096, 1024, 0, 0);

    // QKV fused GEMM -> fp16 q/k/v [proj][b,h,s,e]
    gemmh<0><<<dim3(24, 32), 128, GSMEM>>>(h1h, wqkvh, 1024,
                                           nullptr, qkvh, nullptr, nullptr, 0);

    // tensor-core causal attention -> fp16 concat
    attn_kernel<<<dim3(SS / 64, BB * NH), 128>>>(qkvh, cath);

    // Wo + residual(x) -> attx fp32
    gemmh<1><<<dim3(8, 32), 128, GSMEM>>>(cath, woh, 1024,
                                          attx, nullptr, nullptr, x, DM);

    // LN2 -> fp16
    ln_half_kernel<<<MT, 256>>>(attx, ln2w, ln2b, h2h);

    // FFN1 + bias + exact GELU -> fp16 ff1
    gemmh<2><<<dim3(32, 32), 128, GSMEM>>>(h2h, w1h, 1024,
                                           nullptr, ff1h, b1, nullptr, FF);

    // FFN2 + bias + residual(attx) -> d_out fp32
    gemmh<3><<<dim3(8, 32), 128, GSMEM>>>(ff1h, w2h, 4096,
                                          out, nullptr, b2, attx, DM);
}

// round 17
// speedup vs baseline: 2.5323x; 1.0130x over previous
#include <cuda_runtime.h>
#include <cuda_fp16.h>
#include <mma.h>
#include <math.h>
#include <stdint.h>

using namespace nvcuda;

#define BB 2
#define SS 2048
#define DM 1024
#define NH 16
#define FF 4096
#define MT (BB*SS)   // 4096 rows

// ===================== helpers =====================
__device__ __forceinline__ uint32_t smem_to_u32(const void* p) {
    uint32_t a;
    asm("{ .reg .u64 tmp; cvta.to.shared.u64 tmp, %1; cvt.u32.u64 %0, tmp; }" : "=r"(a) : "l"(p));
    return a;
}
#define CP_ASYNC16(dst, src) \
    asm volatile("cp.async.cg.shared.global [%0], [%1], 16;" :: "r"(dst), "l"(src))
#define CP_COMMIT() asm volatile("cp.async.commit_group;" ::: "memory")
#define CP_WAIT1()  asm volatile("cp.async.wait_group 1;"  ::: "memory")
#define CP_WAIT0()  asm volatile("cp.async.wait_group 0;"  ::: "memory")

#define MMA16816(d, a0, a1, a2, a3, b0, b1) \
    asm volatile("mma.sync.aligned.m16n8k16.row.col.f32.f16.f16.f32 " \
        "{%0,%1,%2,%3}, {%4,%5,%6,%7}, {%8,%9}, {%0,%1,%2,%3};" \
        : "+f"((d)[0]), "+f"((d)[1]), "+f"((d)[2]), "+f"((d)[3]) \
        : "r"(a0), "r"(a1), "r"(a2), "r"(a3), "r"(b0), "r"(b1))

#define LDSM4(r0, r1, r2, r3, addr) \
    asm volatile("ldmatrix.sync.aligned.m8n8.x4.shared.b16 {%0,%1,%2,%3}, [%4];" \
        : "=r"(r0), "=r"(r1), "=r"(r2), "=r"(r3) : "r"(addr))

#define LDSM4T(r0, r1, r2, r3, addr) \
    asm volatile("ldmatrix.sync.aligned.m8n8.x4.trans.shared.b16 {%0,%1,%2,%3}, [%4];" \
        : "=r"(r0), "=r"(r1), "=r"(r2), "=r"(r3) : "r"(addr))

// ===================== scratch =====================
__device__ __half g_h1h[MT*DM];
__device__ __half g_qkvh[(size_t)3*MT*DM];   // [proj][b*NH+h][s][64] fp16
__device__ __half g_cath[MT*DM];
__device__ float  g_attx[MT*DM];
__device__ __half g_h2h[MT*DM];
__device__ __half g_ff1h[(size_t)MT*FF];
__device__ __half g_wqkvh[3*DM*DM];       // [3072 N][1024 K]
__device__ __half g_woh[DM*DM];
__device__ __half g_w1h[(size_t)DM*FF];
__device__ __half g_w2h[(size_t)FF*DM];

// ===================== LayerNorm fp32 -> fp16 =====================
__global__ void ln_half_kernel(const float* __restrict__ x, const float* __restrict__ w,
                               const float* __restrict__ b, __half* __restrict__ o) {
    int row = blockIdx.x;
    int t = threadIdx.x;
    const float4* xr = (const float4*)(x + (size_t)row * DM);
    float4 v = xr[t];
    float s  = v.x + v.y + v.z + v.w;
    float ss = v.x*v.x + v.y*v.y + v.z*v.z + v.w*v.w;
    #pragma unroll
    for (int o2 = 16; o2; o2 >>= 1) {
        s  += __shfl_xor_sync(0xffffffffu, s,  o2);
        ss += __shfl_xor_sync(0xffffffffu, ss, o2);
    }
    __shared__ float red[2][8];
    __shared__ float stats[2];
    int lane = t & 31, wid = t >> 5;
    if (lane == 0) { red[0][wid] = s; red[1][wid] = ss; }
    __syncthreads();
    if (t == 0) {
        float S1 = 0.f, S2 = 0.f;
        #pragma unroll
        for (int i = 0; i < 8; i++) { S1 += red[0][i]; S2 += red[1][i]; }
        float mu  = S1 * (1.f / DM);
        float var = S2 * (1.f / DM) - mu * mu;
        stats[0] = mu; stats[1] = rsqrtf(var + 1e-5f);
    }
    __syncthreads();
    float mu = stats[0], rs = stats[1];
    float4 wv = ((const float4*)w)[t];
    float4 bv = ((const float4*)b)[t];
    float y0 = (v.x - mu) * rs * wv.x + bv.x;
    float y1 = (v.y - mu) * rs * wv.y + bv.y;
    float y2 = (v.z - mu) * rs * wv.z + bv.z;
    float y3 = (v.w - mu) * rs * wv.w + bv.w;
    __half2 p0 = __floats2half2_rn(y0, y1);
    __half2 p1 = __floats2half2_rn(y2, y3);
    *(uint2*)(o + (size_t)row * DM + t * 4) =
        make_uint2(*(uint32_t*)&p0, *(uint32_t*)&p1);
}

// ===================== vectorized transpose fp32 [R,C] -> fp16 [C,R] =====================
// 64x64 tiles, 256 threads. float4 loads, uint2 (4xfp16) stores.
__global__ void t64_kernel(const float* __restrict__ in, __half* __restrict__ o,
                           int R, int C, size_t inBatch, size_t outBatch) {
    in += (size_t)blockIdx.z * inBatch;
    o  += (size_t)blockIdx.z * outBatch;
    __shared__ float s[64][65];
    int c0 = blockIdx.x * 64, r0 = blockIdx.y * 64;
    int tid = threadIdx.x;
    int tr = tid >> 4, tc = tid & 15;          // 16x16 thread grid
    #pragma unroll
    for (int i = 0; i < 4; i++) {
        int row = r0 + tr + i * 16;
        float4 v = *(const float4*)(in + (size_t)row * C + c0 + tc * 4);
        s[tc * 4 + 0][tr + i * 16] = v.x;
        s[tc * 4 + 1][tr + i * 16] = v.y;
        s[tc * 4 + 2][tr + i * 16] = v.z;
        s[tc * 4 + 3][tr + i * 16] = v.w;
    }
    __syncthreads();
    #pragma unroll
    for (int i = 0; i < 4; i++) {
        int oc = tr + i * 16;                  // col within tile (source C index)
        const float* sr = &s[oc][tc * 4];
        __half2 p0 = __floats2half2_rn(sr[0], sr[1]);
        __half2 p1 = __floats2half2_rn(sr[2], sr[3]);
        *(uint2*)(o + (size_t)(c0 + oc) * R + r0 + tc * 4) =
            make_uint2(*(uint32_t*)&p0, *(uint32_t*)&p1);
    }
}

// ===================== fp16 wmma GEMM =====================
// D[M,N] = A[M,K] * B[N,K]^T, fp32 accum. 128x128 CTA, 4 warps 64x64, BK=32, 3-stage.
// EPI: 0 = QKV scatter -> fp16 [proj][b,h,s,e]; 1 = +resid fp32; 2 = +bias GELU fp16; 3 = +bias+resid fp32
#define TILEB   10240
#define STG2    (2*TILEB)
#define GSMEM   67584

template<int EPI>
__global__ __launch_bounds__(128, 2)
void gemmh(const __half* __restrict__ A, const __half* __restrict__ B, int K,
           float* __restrict__ out0, __half* __restrict__ oh,
           const float* __restrict__ bias, const float* __restrict__ resid, int N)
{
    extern __shared__ __align__(16) uint8_t smraw[];
    const uint32_t smb = smem_to_u32(smraw);
    const int tid = threadIdx.x;
    const int wid = tid >> 5;
    const int wm = wid >> 1, wn = wid & 1;
    const int m0 = blockIdx.y * 128;
    const int n0 = blockIdx.x * 128;

    const __half* gsrc[2] = { A + (size_t)m0 * K, B + (size_t)n0 * K };

    wmma::fragment<wmma::accumulator, 16, 16, 16, float> acc[4][4];
    #pragma unroll
    for (int i = 0; i < 4; i++)
        #pragma unroll
        for (int j = 0; j < 4; j++) wmma::fill_fragment(acc[i][j], 0.0f);

    const int NCH = K >> 5;

    auto issue = [&](int ch, int st) {
        int k0 = ch << 5;
        #pragma unroll
        for (int i = 0; i < 8; i++) {
            int idx = i * 128 + tid;
            int t2  = idx >> 9;
            int rem = idx & 511;
            int row = rem >> 2;
            int cch = rem & 3;
            uint32_t dst = smb + st * STG2 + t2 * TILEB + row * 80 + cch * 16;
            const __half* src = gsrc[t2] + (size_t)row * K + k0 + cch * 8;
            CP_ASYNC16(dst, src);
        }
        CP_COMMIT();
    };

    issue(0, 0);
    if (NCH > 1) issue(1, 1);

    for (int ch = 0; ch < NCH; ch++) {
        if (ch == NCH - 1) { CP_WAIT0(); } else { CP_WAIT1(); }
        __syncthreads();
        if (ch + 2 < NCH) issue(ch + 2, (ch + 2) % 3);
        const int st = ch % 3;
        const __half* As = (const __half*)(smraw + st * STG2);
        const __half* Bs = (const __half*)(smraw + st * STG2 + TILEB);
        #pragma unroll
        for (int kk = 0; kk < 32; kk += 16) {
            wmma::fragment<wmma::matrix_a, 16, 16, 16, __half, wmma::row_major> af[4];
            #pragma unroll
            for (int i = 0; i < 4; i++)
                wmma::load_matrix_sync(af[i], As + (wm * 64 + i * 16) * 40 + kk, 40);
            #pragma unroll
            for (int j = 0; j < 4; j++) {
                wmma::fragment<wmma::matrix_b, 16, 16, 16, __half, wmma::col_major> bf;
                wmma::load_matrix_sync(bf, Bs + (wn * 64 + j * 16) * 40 + kk, 40);
                #pragma unroll
                for (int i = 0; i < 4; i++)
                    wmma::mma_sync(acc[i][j], af[i], bf, acc[i][j]);
            }
        }
    }

    __syncthreads();
    float* Cs = (float*)smraw;        // [128][132]
    #pragma unroll
    for (int i = 0; i < 4; i++)
        #pragma unroll
        for (int j = 0; j < 4; j++)
            wmma::store_matrix_sync(Cs + (wm * 64 + i * 16) * 132 + (wn * 64 + j * 16),
                                    acc[i][j], 132, wmma::mem_row_major);
    __syncthreads();

    #pragma unroll
    for (int it = 0; it < 32; it++) {
        int idx = it * 128 + tid;
        int r  = idx >> 5;
        int c4 = (idx & 31) << 2;
        float4 vv = *(const float4*)(Cs + r * 132 + c4);
        int row = m0 + r;
        int c   = n0 + c4;
        if (EPI == 0) {
            int b = row >> 11, sq = row & 2047;
            int proj = c >> 10, cc = c & 1023, hh = cc >> 6, e0 = cc & 63;
            __half2 p0 = __floats2half2_rn(vv.x, vv.y);
            __half2 p1 = __floats2half2_rn(vv.z, vv.w);
            *(uint2*)(oh + ((size_t)(proj * BB * NH + b * NH + hh) * SS + sq) * 64 + e0) =
                make_uint2(*(uint32_t*)&p0, *(uint32_t*)&p1);
        } else if (EPI == 1) {
            float4 r4 = *(const float4*)(resid + (size_t)row * N + c);
            vv.x += r4.x; vv.y += r4.y; vv.z += r4.z; vv.w += r4.w;
            *(float4*)(out0 + (size_t)row * N + c) = vv;
        } else if (EPI == 2) {
            float4 b4 = *(const float4*)(bias + c);
            float o0 = vv.x + b4.x, o1 = vv.y + b4.y, o2 = vv.z + b4.z, o3 = vv.w + b4.w;
            o0 = 0.5f * o0 * (1.f + erff(o0 * 0.70710678118f));
            o1 = 0.5f * o1 * (1.f + erff(o1 * 0.70710678118f));
            o2 = 0.5f * o2 * (1.f + erff(o2 * 0.70710678118f));
            o3 = 0.5f * o3 * (1.f + erff(o3 * 0.70710678118f));
            __half2 p0 = __floats2half2_rn(o0, o1);
            __half2 p1 = __floats2half2_rn(o2, o3);
            *(uint2*)(oh + (size_t)row * N + c) =
                make_uint2(*(uint32_t*)&p0, *(uint32_t*)&p1);
        } else {
            float4 b4 = *(const float4*)(bias + c);
            float4 r4 = *(const float4*)(resid + (size_t)row * N + c);
            vv.x += b4.x + r4.x; vv.y += b4.y + r4.y;
            vv.z += b4.z + r4.z; vv.w += b4.w + r4.w;
            *(float4*)(out0 + (size_t)row * N + c) = vv;
        }
    }
}

// ===================== tensor-core causal flash attention (FA2, mma.sync) =====================
// grid (SS/64, BB*NH), 128 threads (4 warps x 16 query rows). fp16 in/out, fp32 softmax/accum.
// Heavy tiles (large qt) scheduled first via reversed blockIdx.x mapping.
#define KVPITCH 72

__global__ __launch_bounds__(128)
void attn_kernel(const __half* __restrict__ QKV, __half* __restrict__ Oh)
{
    __shared__ __align__(16) __half sm[2][2][64 * KVPITCH];  // [stage][K/V][row*pitch]
    int tid = threadIdx.x;
    int w = tid >> 5, lane = tid & 31;
    int g = lane >> 2, t4 = lane & 3;
    int qt = gridDim.x - 1 - blockIdx.x;       // heavy-first schedule
    int bh = blockIdx.y;
    int qi0 = qt * 64 + w * 16;

    const __half* Qp = QKV + (size_t)bh * SS * 64;
    const __half* Kp = QKV + (size_t)(BB * NH + bh) * SS * 64;
    const __half* Vp = QKV + (size_t)(2 * BB * NH + bh) * SS * 64;

    // Q A-fragments, pre-scaled by 0.125 * log2(e)
    uint32_t qa[4][4];
    {
        __half2 s2 = __float2half2_rn(0.18033688f);
        int r0 = qi0 + g, r1 = r0 + 8;
        #pragma unroll
        for (int t = 0; t < 4; t++) {
            int c0 = t * 16 + t4 * 2;
            __half2 v;
            v = *(const __half2*)(Qp + (size_t)r0 * 64 + c0);     v = __hmul2(v, s2); qa[t][0] = *(uint32_t*)&v;
            v = *(const __half2*)(Qp + (size_t)r1 * 64 + c0);     v = __hmul2(v, s2); qa[t][1] = *(uint32_t*)&v;
            v = *(const __half2*)(Qp + (size_t)r0 * 64 + c0 + 8); v = __hmul2(v, s2); qa[t][2] = *(uint32_t*)&v;
            v = *(const __half2*)(Qp + (size_t)r1 * 64 + c0 + 8); v = __hmul2(v, s2); qa[t][3] = *(uint32_t*)&v;
        }
    }

    float o[8][4];
    #pragma unroll
    for (int j = 0; j < 8; j++)
        #pragma unroll
        for (int c = 0; c < 4; c++) o[j][c] = 0.f;
    float m0 = -INFINITY, m1 = -INFINITY, l0 = 0.f, l1 = 0.f;

    auto loadKV = [&](int kt, int st) {
        const __half* kb = Kp + (size_t)kt * 64 * 64;
        const __half* vb = Vp + (size_t)kt * 64 * 64;
        #pragma unroll
        for (int i = 0; i < 4; i++) {
            int idx = i * 128 + tid;
            int r = idx >> 3, c = idx & 7;
            CP_ASYNC16(smem_to_u32(&sm[st][0][r * KVPITCH + c * 8]), kb + r * 64 + c * 8);
            CP_ASYNC16(smem_to_u32(&sm[st][1][r * KVPITCH + c * 8]), vb + r * 64 + c * 8);
        }
        CP_COMMIT();
    };

    loadKV(0, 0);
    if (qt > 0) loadKV(1, 1);

    for (int kt = 0; kt <= qt; kt++) {
        if (kt == qt) { CP_WAIT0(); } else { CP_WAIT1(); }
        __syncthreads();
        int st = kt & 1;
        const __half* Ks = sm[st][0];
        const __half* Vs = sm[st][1];

        // ---- S = Q K^T (scaled, log2 units) ----
        float s[8][4];
        #pragma unroll
        for (int j = 0; j < 8; j++)
            #pragma unroll
            for (int c = 0; c < 4; c++) s[j][c] = 0.f;
        int blk = lane >> 3, li = lane & 7;
        #pragma unroll
        for (int j2 = 0; j2 < 4; j2++) {
            #pragma unroll
            for (int t = 0; t < 4; t++) {
                uint32_t addr = smem_to_u32(Ks + (8 * (2 * j2 + (blk >> 1)) + li) * KVPITCH
                                               + t * 16 + (blk & 1) * 8);
                uint32_t r0, r1, r2, r3;
                LDSM4(r0, r1, r2, r3, addr);
                MMA16816(s[2 * j2],     qa[t][0], qa[t][1], qa[t][2], qa[t][3], r0, r1);
                MMA16816(s[2 * j2 + 1], qa[t][0], qa[t][1], qa[t][2], qa[t][3], r2, r3);
            }
        }
        // ---- causal mask (diagonal tile only) ----
        if (kt == qt) {
            int rl0 = w * 16 + g, rl1 = rl0 + 8;
            #pragma unroll
            for (int j = 0; j < 8; j++) {
                int key0 = j * 8 + t4 * 2;
                if (key0     > rl0) s[j][0] = -INFINITY;
                if (key0 + 1 > rl0) s[j][1] = -INFINITY;
                if (key0     > rl1) s[j][2] = -INFINITY;
                if (key0 + 1 > rl1) s[j][3] = -INFINITY;
            }
        }
        // ---- online softmax ----
        float tm0 = -INFINITY, tm1 = -INFINITY;
        #pragma unroll
        for (int j = 0; j < 8; j++) {
            tm0 = fmaxf(tm0, fmaxf(s[j][0], s[j][1]));
            tm1 = fmaxf(tm1, fmaxf(s[j][2], s[j][3]));
        }
        tm0 = fmaxf(tm0, __shfl_xor_sync(0xffffffffu, tm0, 1));
        tm0 = fmaxf(tm0, __shfl_xor_sync(0xffffffffu, tm0, 2));
        tm1 = fmaxf(tm1, __shfl_xor_sync(0xffffffffu, tm1, 1));
        tm1 = fmaxf(tm1, __shfl_xor_sync(0xffffffffu, tm1, 2));
        float nm0 = fmaxf(m0, tm0), nm1 = fmaxf(m1, tm1);
        float cr0 = exp2f(m0 - nm0), cr1 = exp2f(m1 - nm1);
        l0 *= cr0; l1 *= cr1;
        #pragma unroll
        for (int j = 0; j < 8; j++) {
            o[j][0] *= cr0; o[j][1] *= cr0;
            o[j][2] *= cr1; o[j][3] *= cr1;
        }
        m0 = nm0; m1 = nm1;

        uint32_t ph[8][2];
        #pragma unroll
        for (int j = 0; j < 8; j++) {
            __half2 h0 = __floats2half2_rn(s[j][0] - nm0, s[j][1] - nm0);
            __half2 h1 = __floats2half2_rn(s[j][2] - nm1, s[j][3] - nm1);
            asm("ex2.approx.f16x2 %0, %1;" : "=r"(ph[j][0]) : "r"(*(uint32_t*)&h0));
            asm("ex2.approx.f16x2 %0, %1;" : "=r"(ph[j][1]) : "r"(*(uint32_t*)&h1));
            float2 f0 = __half22float2(*(__half2*)&ph[j][0]);
            float2 f1 = __half22float2(*(__half2*)&ph[j][1]);
            l0 += f0.x + f0.y;
            l1 += f1.x + f1.y;
        }

        // ---- O += P V ----
        #pragma unroll
        for (int j2 = 0; j2 < 4; j2++) {
            #pragma unroll
            for (int t = 0; t < 4; t++) {
                uint32_t addr = smem_to_u32(Vs + (t * 16 + (blk & 1) * 8 + li) * KVPITCH
                                               + (2 * j2 + (blk >> 1)) * 8);
                uint32_t r0, r1, r2, r3;
                LDSM4T(r0, r1, r2, r3, addr);
                MMA16816(o[2 * j2],     ph[2*t][0], ph[2*t][1], ph[2*t+1][0], ph[2*t+1][1], r0, r1);
                MMA16816(o[2 * j2 + 1], ph[2*t][0], ph[2*t][1], ph[2*t+1][0], ph[2*t+1][1], r2, r3);
            }
        }
        __syncthreads();
        if (kt + 2 <= qt) loadKV(kt + 2, st);
    }

    // ---- finalize ----
    l0 += __shfl_xor_sync(0xffffffffu, l0, 1);
    l0 += __shfl_xor_sync(0xffffffffu, l0, 2);
    l1 += __shfl_xor_sync(0xffffffffu, l1, 1);
    l1 += __shfl_xor_sync(0xffffffffu, l1, 2);
    float inv0 = 1.f / l0, inv1 = 1.f / l1;
    int b = bh >> 4, h = bh & 15;
    int r0 = qi0 + g, r1 = r0 + 8;
    __half* out0 = Oh + (size_t)(b * SS + r0) * DM + h * 64 + t4 * 2;
    __half* out1 = Oh + (size_t)(b * SS + r1) * DM + h * 64 + t4 * 2;
    #pragma unroll
    for (int j = 0; j < 8; j++) {
        __half2 p0 = __floats2half2_rn(o[j][0] * inv0, o[j][1] * inv0);
        __half2 p1 = __floats2half2_rn(o[j][2] * inv1, o[j][3] * inv1);
        *(uint32_t*)(out0 + j * 8) = *(uint32_t*)&p0;
        *(uint32_t*)(out1 + j * 8) = *(uint32_t*)&p1;
    }
}

// ===================== launch =====================
extern "C" void kernel_launch(void* const* d_in, const int* in_sizes, int n_in,
                              void* d_out, int out_size) {
    const float* x    = (const float*)d_in[0];
    const float* Wq   = (const float*)d_in[2];
    const float* Wk   = (const float*)d_in[3];
    const float* Wv   = (const float*)d_in[4];
    const float* Wo   = (const float*)d_in[5];
    const float* ln1w = (const float*)d_in[6];
    const float* ln1b = (const float*)d_in[7];
    const float* ln2w = (const float*)d_in[8];
    const float* ln2b = (const float*)d_in[9];
    const float* W1   = (const float*)d_in[10];
    const float* b1   = (const float*)d_in[11];
    const float* W2   = (const float*)d_in[12];
    const float* b2   = (const float*)d_in[13];
    float* out = (float*)d_out;

    __half *h1h, *qkvh, *cath, *h2h, *ff1h, *wqkvh, *woh, *w1h, *w2h;
    float *attx;
    cudaGetSymbolAddress((void**)&h1h,   g_h1h);
    cudaGetSymbolAddress((void**)&qkvh,  g_qkvh);
    cudaGetSymbolAddress((void**)&cath,  g_cath);
    cudaGetSymbolAddress((void**)&attx,  g_attx);
    cudaGetSymbolAddress((void**)&h2h,   g_h2h);
    cudaGetSymbolAddress((void**)&ff1h,  g_ff1h);
    cudaGetSymbolAddress((void**)&wqkvh, g_wqkvh);
    cudaGetSymbolAddress((void**)&woh,   g_woh);
    cudaGetSymbolAddress((void**)&w1h,   g_w1h);
    cudaGetSymbolAddress((void**)&w2h,   g_w2h);

    cudaFuncSetAttribute(gemmh<0>, cudaFuncAttributeMaxDynamicSharedMemorySize, GSMEM);
    cudaFuncSetAttribute(gemmh<1>, cudaFuncAttributeMaxDynamicSharedMemorySize, GSMEM);
    cudaFuncSetAttribute(gemmh<2>, cudaFuncAttributeMaxDynamicSharedMemorySize, GSMEM);
    cudaFuncSetAttribute(gemmh<3>, cudaFuncAttributeMaxDynamicSharedMemorySize, GSMEM);

    // LN1 -> fp16
    ln_half_kernel<<<MT, 256>>>(x, ln1w, ln1b, h1h);

    // weight transpose -> fp16 [N,K] (vectorized 64x64 tiles)
    t64_kernel<<<dim3(1, 16, 16), 256>>>(Wq, wqkvh,               1024, 64, (size_t)1024*64, (size_t)64*1024);
    t64_kernel<<<dim3(1, 16, 16), 256>>>(Wk, wqkvh + 1024*1024,   1024, 64, (size_t)1024*64, (size_t)64*1024);
    t64_kernel<<<dim3(1, 16, 16), 256>>>(Wv, wqkvh + 2*1024*1024, 1024, 64, (size_t)1024*64, (size_t)64*1024);
    t64_kernel<<<dim3(16, 16, 1), 256>>>(Wo, woh, 1024, 1024, 0, 0);
    t64_kernel<<<dim3(64, 16, 1), 256>>>(W1, w1h, 1024, 4096, 0, 0);
    t64_kernel<<<dim3(16, 64, 1), 256>>>(W2, w2h, 4096, 1024, 0, 0);

    // QKV fused GEMM -> fp16 q/k/v [proj][b,h,s,e]
    gemmh<0><<<dim3(24, 32), 128, GSMEM>>>(h1h, wqkvh, 1024,
                                           nullptr, qkvh, nullptr, nullptr, 0);

    // tensor-core causal attention -> fp16 concat
    attn_kernel<<<dim3(SS / 64, BB * NH), 128>>>(qkvh, cath);

    // Wo + residual(x) -> attx fp32
    gemmh<1><<<dim3(8, 32), 128, GSMEM>>>(cath, woh, 1024,
                                          attx, nullptr, nullptr, x, DM);

    // LN2 -> fp16
    ln_half_kernel<<<MT, 256>>>(attx, ln2w, ln2b, h2h);

    // FFN1 + bias + exact GELU -> fp16 ff1
    gemmh<2><<<dim3(32, 32), 128, GSMEM>>>(h2h, w1h, 1024,
                                           nullptr, ff1h, b1, nullptr, FF);

    // FFN2 + bias + residual(attx) -> d_out fp32
    gemmh<3><<<dim3(8, 32), 128, GSMEM>>>(ff1h, w2h, 4096,
                                          out, nullptr, b2, attx, DM);
}